// round 3
// baseline (speedup 1.0000x reference)
#include <cuda_runtime.h>
#include <cstdint>

// RoiPoolingConv: img [1,256,256,512] f32 (NHWC), rois [1,1024,4] i32 (x1,y1,x2,y2)
// out [1,1024,7,7,512] f32 — TF1-legacy bilinear crop-resize to 7x7.
//
// One block per (roi, pooled position). 128 threads x float4 = 512 channels.

#define POOL 7
#define IMG_W 256
#define IMG_C 512
#define NVEC (IMG_C / 4)   // 128 float4 per pixel

__global__ __launch_bounds__(NVEC)
void roi_pool_kernel(const float* __restrict__ img,
                     const int*   __restrict__ rois,
                     float*       __restrict__ out)
{
    const int pos = blockIdx.x;          // 0..48
    const int roi = blockIdx.y;          // 0..1023
    const int py  = pos / POOL;
    const int px  = pos - py * POOL;

    // ROI descriptor: 16B aligned, uniform across block (L1 broadcast)
    const int4 r = __ldg(reinterpret_cast<const int4*>(rois) + roi);
    const int x1 = r.x, y1 = r.y, x2 = r.z, y2 = r.w;

    const float h = (float)(y2 - y1);
    const float w = (float)(x2 - x1);

    // Reference op order: (h / P) first, then scale by index.
    const float ys = (float)py * (h / 7.0f);
    const float xs = (float)px * (w / 7.0f);

    const int y0 = (int)floorf(ys);
    const int x0 = (int)floorf(xs);
    const int ymax = max(y2 - y1 - 1, 0);
    const int xmax = max(x2 - x1 - 1, 0);
    const int y1i = min(y0 + 1, ymax);
    const int x1i = min(x0 + 1, xmax);

    const float wy = ys - (float)y0;
    const float wx = xs - (float)x0;

    const float w00 = (1.0f - wy) * (1.0f - wx);
    const float w01 = (1.0f - wy) * wx;
    const float w10 = wy * (1.0f - wx);
    const float w11 = wy * wx;

    const int row0 = y1 + y0;
    const int row1 = y1 + y1i;
    const int col0 = x1 + x0;
    const int col1 = x1 + x1i;

    const float4* __restrict__ p00 =
        reinterpret_cast<const float4*>(img) + ((size_t)row0 * IMG_W + col0) * NVEC;
    const float4* __restrict__ p01 =
        reinterpret_cast<const float4*>(img) + ((size_t)row0 * IMG_W + col1) * NVEC;
    const float4* __restrict__ p10 =
        reinterpret_cast<const float4*>(img) + ((size_t)row1 * IMG_W + col0) * NVEC;
    const float4* __restrict__ p11 =
        reinterpret_cast<const float4*>(img) + ((size_t)row1 * IMG_W + col1) * NVEC;

    const int c = threadIdx.x;           // 0..127 (float4 index)

    const float4 v00 = __ldg(p00 + c);
    const float4 v01 = __ldg(p01 + c);
    const float4 v10 = __ldg(p10 + c);
    const float4 v11 = __ldg(p11 + c);

    float4 o;
    o.x = fmaf(v00.x, w00, fmaf(v01.x, w01, fmaf(v10.x, w10, v11.x * w11)));
    o.y = fmaf(v00.y, w00, fmaf(v01.y, w01, fmaf(v10.y, w10, v11.y * w11)));
    o.z = fmaf(v00.z, w00, fmaf(v01.z, w01, fmaf(v10.z, w10, v11.z * w11)));
    o.w = fmaf(v00.w, w00, fmaf(v01.w, w01, fmaf(v10.w, w10, v11.w * w11)));

    float4* __restrict__ optr =
        reinterpret_cast<float4*>(out) + ((size_t)roi * (POOL * POOL) + pos) * NVEC;
    optr[c] = o;
}

extern "C" void kernel_launch(void* const* d_in, const int* in_sizes, int n_in,
                              void* d_out, int out_size)
{
    const float* img  = (const float*)d_in[0];   // [1,256,256,512] f32
    const int*   rois = (const int*)d_in[1];     // [1,1024,4] i32
    float*       out  = (float*)d_out;           // [1,1024,7,7,512] f32

    dim3 grid(POOL * POOL, 1024);
    roi_pool_kernel<<<grid, NVEC>>>(img, rois, out);
}

// round 4
// speedup vs baseline: 1.0255x; 1.0255x over previous
#include <cuda_runtime.h>
#include <cstdint>

// RoiPoolingConv: img [1,256,256,512] f32 (NHWC), rois [1,1024,4] i32 (x1,y1,x2,y2)
// out [1,1024,7,7,512] f32 — TF1-legacy bilinear crop-resize to 7x7.
//
// One block per (roi, pooled position). 128 threads x float4 = 512 channels.
// R3: skip zero-weight taps (uniform per block), streaming stores to keep L2
// capacity for the image.

#define POOL 7
#define IMG_W 256
#define IMG_C 512
#define NVEC (IMG_C / 4)   // 128 float4 per pixel

__global__ __launch_bounds__(NVEC)
void roi_pool_kernel(const float* __restrict__ img,
                     const int*   __restrict__ rois,
                     float*       __restrict__ out)
{
    const int pos = blockIdx.x;          // 0..48
    const int roi = blockIdx.y;          // 0..1023
    const int py  = pos / POOL;
    const int px  = pos - py * POOL;

    // ROI descriptor: 16B aligned, uniform across block (L1 broadcast)
    const int4 r = __ldg(reinterpret_cast<const int4*>(rois) + roi);
    const int x1 = r.x, y1 = r.y, x2 = r.z, y2 = r.w;

    const float h = (float)(y2 - y1);
    const float w = (float)(x2 - x1);

    // Reference op order: (h / P) first, then scale by index.
    const float ys = (float)py * (h / 7.0f);
    const float xs = (float)px * (w / 7.0f);

    const int y0 = (int)floorf(ys);
    const int x0 = (int)floorf(xs);
    const int ymax = max(y2 - y1 - 1, 0);
    const int xmax = max(x2 - x1 - 1, 0);
    const int y1i = min(y0 + 1, ymax);
    const int x1i = min(x0 + 1, xmax);

    const float wy = ys - (float)y0;
    const float wx = xs - (float)x0;

    const float w00 = (1.0f - wy) * (1.0f - wx);
    const float w01 = (1.0f - wy) * wx;
    const float w10 = wy * (1.0f - wx);
    const float w11 = wy * wx;

    // Uniform across the block: which taps carry nonzero weight.
    const bool need_r1 = (wy != 0.0f);   // row1 taps (w10, w11)
    const bool need_c1 = (wx != 0.0f);   // col1 taps (w01, w11)

    const int row0 = y1 + y0;
    const int row1 = y1 + y1i;
    const int col0 = x1 + x0;
    const int col1 = x1 + x1i;

    const float4* __restrict__ base = reinterpret_cast<const float4*>(img);
    const int c = threadIdx.x;           // 0..127 (float4 index)

    const float4* p00 = base + ((size_t)row0 * IMG_W + col0) * NVEC + c;

    const float4 v00 = __ldg(p00);
    float4 o;
    o.x = v00.x * w00;
    o.y = v00.y * w00;
    o.z = v00.z * w00;
    o.w = v00.w * w00;

    if (need_c1) {
        const float4 v01 = __ldg(base + ((size_t)row0 * IMG_W + col1) * NVEC + c);
        o.x = fmaf(v01.x, w01, o.x);
        o.y = fmaf(v01.y, w01, o.y);
        o.z = fmaf(v01.z, w01, o.z);
        o.w = fmaf(v01.w, w01, o.w);
    }
    if (need_r1) {
        const float4 v10 = __ldg(base + ((size_t)row1 * IMG_W + col0) * NVEC + c);
        o.x = fmaf(v10.x, w10, o.x);
        o.y = fmaf(v10.y, w10, o.y);
        o.z = fmaf(v10.z, w10, o.z);
        o.w = fmaf(v10.w, w10, o.w);
        if (need_c1) {
            const float4 v11 = __ldg(base + ((size_t)row1 * IMG_W + col1) * NVEC + c);
            o.x = fmaf(v11.x, w11, o.x);
            o.y = fmaf(v11.y, w11, o.y);
            o.z = fmaf(v11.z, w11, o.z);
            o.w = fmaf(v11.w, w11, o.w);
        }
    }

    // Streaming store: output is write-once, keep it out of L2's way.
    float4* optr = reinterpret_cast<float4*>(out)
                 + ((size_t)roi * (POOL * POOL) + pos) * NVEC + c;
    __stcs(optr, o);
}

extern "C" void kernel_launch(void* const* d_in, const int* in_sizes, int n_in,
                              void* d_out, int out_size)
{
    const float* img  = (const float*)d_in[0];   // [1,256,256,512] f32
    const int*   rois = (const int*)d_in[1];     // [1,1024,4] i32
    float*       out  = (float*)d_out;           // [1,1024,7,7,512] f32

    dim3 grid(POOL * POOL, 1024);
    roi_pool_kernel<<<grid, NVEC>>>(img, rois, out);
}

// round 5
// speedup vs baseline: 1.0391x; 1.0133x over previous
#include <cuda_runtime.h>
#include <cstdint>

// RoiPoolingConv: img [1,256,256,512] f32 (NHWC), rois [1,1024,4] i32 (x1,y1,x2,y2)
// out [1,1024,7,7,512] f32 — TF1-legacy bilinear crop-resize to 7x7.
//
// R4: one block per (roi, py) ROW. 128 threads x float4 = 512 channels.
// 7 px positions fully unrolled with unconditional 4-tap loads -> ~28
// independent LDG.128 per thread for deep memory-level parallelism; blocks
// live long enough to amortize load latency instead of dying on it.

#define POOL 7
#define IMG_W 256
#define IMG_C 512
#define NVEC (IMG_C / 4)   // 128 float4 per pixel

__global__ __launch_bounds__(NVEC, 8)
void roi_pool_row_kernel(const float* __restrict__ img,
                         const int*   __restrict__ rois,
                         float*       __restrict__ out)
{
    const int py  = blockIdx.x;          // 0..6
    const int roi = blockIdx.y;          // 0..1023

    // ROI descriptor: 16B aligned, uniform across block
    const int4 r = __ldg(reinterpret_cast<const int4*>(rois) + roi);
    const int x1 = r.x, y1 = r.y, x2 = r.z, y2 = r.w;

    const float h = (float)(y2 - y1);
    const float w = (float)(x2 - x1);

    // Reference op order: (h / P) first, then scale by index.
    const float ys = (float)py * (h / 7.0f);
    const int   y0 = (int)floorf(ys);
    const int ymax = max(y2 - y1 - 1, 0);
    const int xmax = max(x2 - x1 - 1, 0);
    const int  y1i = min(y0 + 1, ymax);
    const float wy = ys - (float)y0;

    const int row0 = y1 + y0;
    const int row1 = y1 + y1i;

    const float4* __restrict__ base = reinterpret_cast<const float4*>(img);
    const float4* __restrict__ b0 = base + (size_t)row0 * IMG_W * NVEC;
    const float4* __restrict__ b1 = base + (size_t)row1 * IMG_W * NVEC;

    const int c = threadIdx.x;           // 0..127 (float4 index within channels)

    float4* __restrict__ orow = reinterpret_cast<float4*>(out)
                              + ((size_t)roi * (POOL * POOL) + (size_t)py * POOL) * NVEC + c;

    const float w_over_7 = w / 7.0f;

#pragma unroll
    for (int px = 0; px < POOL; ++px) {
        const float xs = (float)px * w_over_7;
        const int   x0 = (int)floorf(xs);
        const int  x1i = min(x0 + 1, xmax);
        const float wx = xs - (float)x0;

        const float w00 = (1.0f - wy) * (1.0f - wx);
        const float w01 = (1.0f - wy) * wx;
        const float w10 = wy * (1.0f - wx);
        const float w11 = wy * wx;

        const int col0 = x1 + x0;
        const int col1 = x1 + x1i;

        const float4 v00 = __ldg(b0 + (size_t)col0 * NVEC + c);
        const float4 v01 = __ldg(b0 + (size_t)col1 * NVEC + c);
        const float4 v10 = __ldg(b1 + (size_t)col0 * NVEC + c);
        const float4 v11 = __ldg(b1 + (size_t)col1 * NVEC + c);

        float4 o;
        o.x = fmaf(v00.x, w00, fmaf(v01.x, w01, fmaf(v10.x, w10, v11.x * w11)));
        o.y = fmaf(v00.y, w00, fmaf(v01.y, w01, fmaf(v10.y, w10, v11.y * w11)));
        o.z = fmaf(v00.z, w00, fmaf(v01.z, w01, fmaf(v10.z, w10, v11.z * w11)));
        o.w = fmaf(v00.w, w00, fmaf(v01.w, w01, fmaf(v10.w, w10, v11.w * w11)));

        __stcs(orow + (size_t)px * NVEC, o);
    }
}

extern "C" void kernel_launch(void* const* d_in, const int* in_sizes, int n_in,
                              void* d_out, int out_size)
{
    const float* img  = (const float*)d_in[0];   // [1,256,256,512] f32
    const int*   rois = (const int*)d_in[1];     // [1,1024,4] i32
    float*       out  = (float*)d_out;           // [1,1024,7,7,512] f32

    dim3 grid(POOL, 1024);
    roi_pool_row_kernel<<<grid, NVEC>>>(img, rois, out);
}